// round 16
// baseline (speedup 1.0000x reference)
#include <cuda_runtime.h>
#include <cuda_fp16.h>
#include <mma.h>
#include <math.h>

using namespace nvcuda;

// GATNET: N=20000, E=640000, IN=256, H=4, OUT=64
#define NN   20000
#define EE   640000
#define ET   (EE + NN)
#define KIN  256
#define HC   256
#define H1   4
#define C1   64
#define C2   64
#define MAXD 128     // max in-degree bucket (deg ~ Poisson(33); P(>127) ~ 1e-40; guarded)

__device__ __half g_xh[NN * KIN];
__device__ __half g_w1h[KIN * HC];
__device__ __half g_w2h[HC * C2];
__device__ __half g_h1h[NN * HC];
__device__ __half g_x1h[NN * HC];
__device__ __half g_h2h[NN * C2];
__device__ float  g_as1[NN * H1];
__device__ float  g_ad1[NN * H1];
__device__ float  g_as2[NN];
__device__ float  g_ad2[NN];
__device__ int    g_cnt[NN];
__device__ int    g_buck[NN * MAXD];        // per-dst src lists
__device__ float  g_w1c[NN * MAXD * H1];    // per-(dst,slot,head) weights
__device__ float  g_w2c[NN * MAXD];
__device__ int    g_is64;

// ---------------- fast exp (FMA pipe only) ----------------
__device__ __forceinline__ float fexp(float x) {
    float y = x * 1.4426950408889634f;
    float n = rintf(y);
    float t = fmaf(-n, 0.6931471805599453f, x);
    float p = fmaf(t, 0.041666667f, 0.166666667f);
    p = fmaf(t, p, 0.5f);
    p = fmaf(t, p, 1.0f);
    p = fmaf(t, p, 1.0f);
    int e = (((int)n) + 127) << 23;
    return p * __int_as_float(e);
}

// ---------------- fp32 -> fp16 ----------------
__global__ void f2h_k(const float* __restrict__ src, __half* __restrict__ dst, int n4) {
    int i = blockIdx.x * blockDim.x + threadIdx.x;
    if (i >= n4) return;
    float4 v = ((const float4*)src)[i];
    __half2* d = (__half2*)dst + i * 2;
    d[0] = __floats2half2_rn(v.x, v.y);
    d[1] = __floats2half2_rn(v.z, v.w);
}

// ---------------- dtype probe + zero counts (fused) ----------------
__global__ void detect_zero_k(const long long* __restrict__ ei64) {
    int t = blockIdx.x * blockDim.x + threadIdx.x;
    if (t < NN) g_cnt[t] = 0;
    if (blockIdx.x == 0) {
        __shared__ int bad;
        if (threadIdx.x == 0) bad = 0;
        __syncthreads();
        for (int i = threadIdx.x; i < 2048; i += blockDim.x) {
            long long v = ei64[i];
            if (v < 0 || v >= NN) bad = 1;
        }
        __syncthreads();
        if (threadIdx.x == 0) g_is64 = bad ? 0 : 1;
    }
}

__device__ __forceinline__ void load_edge(const void* __restrict__ ei, int e, int& s, int& d) {
    if (e >= EE) { s = d = e - EE; return; }
    if (g_is64) {
        const long long* p = (const long long*)ei;
        s = (int)p[e]; d = (int)p[EE + e];
    } else {
        const int* p = (const int*)ei;
        s = p[e]; d = p[EE + e];
    }
}

// ---------------- one-pass bucketing (replaces count+scan+scatter) ----------------
__global__ void bucket_k(const void* __restrict__ ei) {
    int e = blockIdx.x * blockDim.x + threadIdx.x;
    if (e >= ET) return;
    int s, d; load_edge(ei, e, s, d);
    if ((unsigned)d < NN && (unsigned)s < NN) {
        int pos = atomicAdd(&g_cnt[d], 1);
        if (pos < MAXD) g_buck[d * MAXD + pos] = s;
    }
}

// ---------------- fp16 WMMA GEMM 64x64 (BK=32) + fused logits epilogue ----------------
#define BK32 32
__global__ __launch_bounds__(256) void hgemm_fused_k(const __half* __restrict__ A,
                                                     const __half* __restrict__ B,
                                                     __half* __restrict__ Ch,
                                                     const float* __restrict__ attS,
                                                     const float* __restrict__ attD,
                                                     float* __restrict__ asOut,
                                                     float* __restrict__ adOut,
                                                     int HS,
                                                     int M, int N, int K) {
    __shared__ __half Ah[64][48];
    __shared__ __half Bh[32][80];
    __shared__ float  Cs[64][68];
    const int bn = blockIdx.x * 64;
    const int bm = blockIdx.y * 64;
    const int tid = threadIdx.x;
    const int w = tid >> 5;
    const int wm = (w >> 1) * 16;
    const int wn = (w & 1) * 32;

    wmma::fragment<wmma::accumulator, 16, 16, 16, float> c0, c1;
    wmma::fill_fragment(c0, 0.f);
    wmma::fill_fragment(c1, 0.f);

    for (int k0 = 0; k0 < K; k0 += BK32) {
        {
            int row = tid >> 2, col8 = (tid & 3) * 8;
            int gm = bm + row;
            float4 v = make_float4(0.f, 0.f, 0.f, 0.f);
            if (gm < M) v = *(const float4*)&A[(size_t)gm * K + k0 + col8];
            *(float4*)&Ah[row][col8] = v;
        }
        {
            int row = tid >> 3, col8 = (tid & 7) * 8;
            *(float4*)&Bh[row][col8] = *(const float4*)&B[(size_t)(k0 + row) * N + bn + col8];
        }
        __syncthreads();
        wmma::fragment<wmma::matrix_a, 16, 16, 16, __half, wmma::row_major> af;
        wmma::fragment<wmma::matrix_b, 16, 16, 16, __half, wmma::row_major> b0, b1;
#pragma unroll
        for (int kk = 0; kk < BK32; kk += 16) {
            wmma::load_matrix_sync(af, &Ah[wm][kk], 48);
            wmma::load_matrix_sync(b0, &Bh[kk][wn], 80);
            wmma::load_matrix_sync(b1, &Bh[kk][wn + 16], 80);
            wmma::mma_sync(c0, af, b0, c0);
            wmma::mma_sync(c1, af, b1, c1);
        }
        __syncthreads();
    }

    wmma::store_matrix_sync(&Cs[wm][wn],      c0, 68, wmma::mem_row_major);
    wmma::store_matrix_sync(&Cs[wm][wn + 16], c1, 68, wmma::mem_row_major);
    __syncthreads();

    const int tx = tid & 15, ty = tid >> 4;
    float asv[4], adv[4];
#pragma unroll
    for (int j = 0; j < 4; j++) {
        asv[j] = attS[bn + tx * 4 + j];
        adv[j] = attD[bn + tx * 4 + j];
    }
    const int h = blockIdx.x;
#pragma unroll
    for (int i = 0; i < 4; i++) {
        int gm = bm + ty * 4 + i;
        float a0 = Cs[ty * 4 + i][tx * 4 + 0];
        float a1 = Cs[ty * 4 + i][tx * 4 + 1];
        float a2 = Cs[ty * 4 + i][tx * 4 + 2];
        float a3 = Cs[ty * 4 + i][tx * 4 + 3];
        float s = a0 * asv[0] + a1 * asv[1] + a2 * asv[2] + a3 * asv[3];
        float d = a0 * adv[0] + a1 * adv[1] + a2 * adv[2] + a3 * adv[3];
#pragma unroll
        for (int o = 8; o; o >>= 1) {
            s += __shfl_down_sync(0xffffffffu, s, o, 16);
            d += __shfl_down_sync(0xffffffffu, d, o, 16);
        }
        if (gm < M) {
            if (tx == 0) {
                asOut[(size_t)gm * HS + h] = s;
                adOut[(size_t)gm * HS + h] = d;
            }
            __half2* hp = (__half2*)&Ch[(size_t)gm * N + bn + tx * 4];
            hp[0] = __floats2half2_rn(a0, a1);
            hp[1] = __floats2half2_rn(a2, a3);
        }
    }
}

// ---------------- gat1: edge softmax + 8-edge-wide fp16 gather ----------------
__global__ __launch_bounds__(256) void gat1_k(const float* __restrict__ bias1) {
    const int d = blockIdx.x;
    const int tid = threadIdx.x;
    const int cnt = min(g_cnt[d], MAXD);
    const int base = d * MAXD;

    // pass 1: weights + denominators
    float loc[H1] = {0.f, 0.f, 0.f, 0.f};
    const int items = cnt * H1;
    for (int i = tid; i < items; i += 256) {
        int j = i >> 2;
        int h = i & 3;
        int s = g_buck[base + j];
        float x = g_as1[s * H1 + h] + g_ad1[d * H1 + h];
        x = (x > 0.f) ? x : 0.2f * x;
        x = fmaxf(x, -60.f);
        float w = fexp(x);
        g_w1c[(base + j) * H1 + h] = w;
        loc[h] += w;
    }
#pragma unroll
    for (int h = 0; h < H1; h++)
#pragma unroll
        for (int o = 16; o; o >>= 1) loc[h] += __shfl_down_sync(0xffffffffu, loc[h], o);
    __shared__ float sw[8][H1];
    if ((tid & 31) == 0)
#pragma unroll
        for (int h = 0; h < H1; h++) sw[tid >> 5][h] = loc[h];
    __syncthreads();
    __shared__ float sinv[H1];
    if (tid < H1) {
        float s = 0.f;
#pragma unroll
        for (int w = 0; w < 8; w++) s += sw[w][tid];
        sinv[tid] = 1.0f / (s + 1e-16f);
    }
    __syncthreads();

    // pass 2: 8 edge streams (eo), each thread handles 8 features (16B uint4)
    const int eo = tid >> 5;            // 0..7
    const int fi = tid & 31;            // feature octet: f = fi*8 .. fi*8+7
    const int h  = fi >> 3;             // head (64 feats per head)
    float acc[8] = {};
    for (int j = eo; j < cnt; j += 8) {
        int s = g_buck[base + j];
        float w = g_w1c[(base + j) * H1 + h];
        uint4 raw = *(const uint4*)&g_h1h[(size_t)s * HC + fi * 8];
        const __half2* hv = (const __half2*)&raw;
#pragma unroll
        for (int q = 0; q < 4; q++) {
            float2 v = __half22float2(hv[q]);
            acc[q * 2]     += w * v.x;
            acc[q * 2 + 1] += w * v.y;
        }
    }
    // reduce the 8 eo-streams
    __shared__ float red[256][8];
#pragma unroll
    for (int q = 0; q < 8; q++) red[tid][q] = acc[q];
    __syncthreads();
#pragma unroll
    for (int st = 4; st >= 1; st >>= 1) {
        if (eo < st) {
#pragma unroll
            for (int q = 0; q < 8; q++)
                red[tid][q] += red[tid + st * 32][q];
        }
        __syncthreads();
    }
    if (eo == 0) {
        const float inv = sinv[h];
        __half2 outv[4];
#pragma unroll
        for (int q = 0; q < 4; q++) {
            float v0 = red[tid][q * 2]     * inv + bias1[fi * 8 + q * 2];
            float v1 = red[tid][q * 2 + 1] * inv + bias1[fi * 8 + q * 2 + 1];
            v0 = (v0 > 0.f) ? v0 : expm1f(v0);
            v1 = (v1 > 0.f) ? v1 : expm1f(v1);
            outv[q] = __floats2half2_rn(v0, v1);
        }
        *(uint4*)&g_x1h[(size_t)d * HC + fi * 8] = *(uint4*)outv;
    }
}

// ---------------- gat2: edge softmax + 8-edge-wide fp16 gather ----------------
__global__ __launch_bounds__(64) void gat2_k(const float* __restrict__ bias2,
                                             float* __restrict__ out) {
    const int d = blockIdx.x;
    const int tid = threadIdx.x;
    const int cnt = min(g_cnt[d], MAXD);
    const int base = d * MAXD;

    float loc = 0.f;
    const float ad = g_ad2[d];
    for (int i = tid; i < cnt; i += 64) {
        int s = g_buck[base + i];
        float x = g_as2[s] + ad;
        x = (x > 0.f) ? x : 0.2f * x;
        x = fmaxf(x, -60.f);
        float w = fexp(x);
        g_w2c[base + i] = w;
        loc += w;
    }
#pragma unroll
    for (int o = 16; o; o >>= 1) loc += __shfl_down_sync(0xffffffffu, loc, o);
    __shared__ float sw2[2];
    if ((tid & 31) == 0) sw2[tid >> 5] = loc;
    __syncthreads();
    __shared__ float sinv2;
    if (tid == 0) sinv2 = 1.0f / (sw2[0] + sw2[1] + 1e-16f);
    __syncthreads();

    // 8 edge streams, 8 features per thread
    const int eo = tid >> 3;            // 0..7
    const int fi = tid & 7;             // f = fi*8 .. fi*8+7
    float acc[8] = {};
    for (int j = eo; j < cnt; j += 8) {
        int s = g_buck[base + j];
        float w = g_w2c[base + j];
        uint4 raw = *(const uint4*)&g_h2h[(size_t)s * C2 + fi * 8];
        const __half2* hv = (const __half2*)&raw;
#pragma unroll
        for (int q = 0; q < 4; q++) {
            float2 v = __half22float2(hv[q]);
            acc[q * 2]     += w * v.x;
            acc[q * 2 + 1] += w * v.y;
        }
    }
    __shared__ float red[64][8];
#pragma unroll
    for (int q = 0; q < 8; q++) red[tid][q] = acc[q];
    __syncthreads();
#pragma unroll
    for (int st = 4; st >= 1; st >>= 1) {
        if (eo < st) {
#pragma unroll
            for (int q = 0; q < 8; q++)
                red[tid][q] += red[tid + st * 8][q];
        }
        __syncthreads();
    }
    if (eo == 0) {
        const float inv = sinv2;
        float4 o0, o1;
        o0.x = red[tid][0] * inv + bias2[fi * 8 + 0];
        o0.y = red[tid][1] * inv + bias2[fi * 8 + 1];
        o0.z = red[tid][2] * inv + bias2[fi * 8 + 2];
        o0.w = red[tid][3] * inv + bias2[fi * 8 + 3];
        o1.x = red[tid][4] * inv + bias2[fi * 8 + 4];
        o1.y = red[tid][5] * inv + bias2[fi * 8 + 5];
        o1.z = red[tid][6] * inv + bias2[fi * 8 + 6];
        o1.w = red[tid][7] * inv + bias2[fi * 8 + 7];
        *(float4*)&out[(size_t)d * C2 + fi * 8]     = o0;
        *(float4*)&out[(size_t)d * C2 + fi * 8 + 4] = o1;
    }
}

// ---------------- launch ----------------
extern "C" void kernel_launch(void* const* d_in, const int* in_sizes, int n_in,
                              void* d_out, int out_size) {
    const float* x   = (const float*)d_in[0];
    const void*  ei  = d_in[1];
    const float* W1  = (const float*)d_in[2];
    const float* as1 = (const float*)d_in[3];
    const float* ad1 = (const float*)d_in[4];
    const float* b1  = (const float*)d_in[5];
    const float* W2  = (const float*)d_in[6];
    const float* as2 = (const float*)d_in[7];
    const float* ad2 = (const float*)d_in[8];
    const float* b2  = (const float*)d_in[9];
    float* out = (float*)d_out;

    // R7 root cause: resolve true device addresses of __device__ symbols
    // used as kernel args (host-shadow writes are silently absorbed via ATS).
    __half *xhp, *w1hp, *w2hp, *h1hp, *x1hp, *h2hp;
    float  *as1p, *ad1p, *as2p, *ad2p;
    cudaGetSymbolAddress((void**)&xhp,  g_xh);
    cudaGetSymbolAddress((void**)&w1hp, g_w1h);
    cudaGetSymbolAddress((void**)&w2hp, g_w2h);
    cudaGetSymbolAddress((void**)&h1hp, g_h1h);
    cudaGetSymbolAddress((void**)&x1hp, g_x1h);
    cudaGetSymbolAddress((void**)&h2hp, g_h2h);
    cudaGetSymbolAddress((void**)&as1p, g_as1);
    cudaGetSymbolAddress((void**)&ad1p, g_ad1);
    cudaGetSymbolAddress((void**)&as2p, g_as2);
    cudaGetSymbolAddress((void**)&ad2p, g_ad2);

    detect_zero_k<<<(NN + 255) / 256, 256>>>((const long long*)ei);
    bucket_k<<<(ET + 255) / 256, 256>>>(ei);

    f2h_k<<<(NN * KIN / 4 + 255) / 256, 256>>>(x, xhp, NN * KIN / 4);
    f2h_k<<<(KIN * HC / 4 + 255) / 256, 256>>>(W1, w1hp, KIN * HC / 4);
    f2h_k<<<(HC * C2 / 4 + 255) / 256, 256>>>(W2, w2hp, HC * C2 / 4);

    // layer 1
    { dim3 g(HC / 64, (NN + 63) / 64);
      hgemm_fused_k<<<g, 256>>>(xhp, w1hp, h1hp, as1, ad1, as1p, ad1p, H1, NN, HC, KIN); }
    gat1_k<<<NN, 256>>>(b1);

    // layer 2
    { dim3 g(C2 / 64, (NN + 63) / 64);
      hgemm_fused_k<<<g, 256>>>(x1hp, w2hp, h2hp, as2, ad2, as2p, ad2p, 1, NN, C2, HC); }
    gat2_k<<<NN, 64>>>(b2, out);
}

// round 17
// speedup vs baseline: 1.5114x; 1.5114x over previous
#include <cuda_runtime.h>
#include <cuda_fp16.h>
#include <mma.h>
#include <math.h>

using namespace nvcuda;

// GATNET: N=20000, E=640000, IN=256, H=4, OUT=64
#define NN   20000
#define EE   640000
#define ET   (EE + NN)
#define KIN  256
#define HC   256
#define H1   4
#define C1   64
#define C2   64
#define MAXD 128     // max in-degree (deg = Poisson(32)+1; max over 20000 nodes ~ 70)

__device__ __half g_xh[NN * KIN];
__device__ __half g_w1h[KIN * HC];
__device__ __half g_w2h[HC * C2];
__device__ __half g_h1h[NN * HC];
__device__ __half g_x1h[NN * HC];
__device__ __half g_h2h[NN * C2];
__device__ float  g_as1[NN * H1];
__device__ float  g_ad1[NN * H1];
__device__ float  g_as2[NN];
__device__ float  g_ad2[NN];
__device__ int    g_cnt[NN];
__device__ int    g_buck[NN * MAXD];
__device__ float  g_w1c[NN * MAXD * H1];
__device__ float  g_w2c[NN * MAXD];
__device__ int    g_is64;

// ---------------- fast exp (FMA pipe only) ----------------
__device__ __forceinline__ float fexp(float x) {
    float y = x * 1.4426950408889634f;
    float n = rintf(y);
    float t = fmaf(-n, 0.6931471805599453f, x);
    float p = fmaf(t, 0.041666667f, 0.166666667f);
    p = fmaf(t, p, 0.5f);
    p = fmaf(t, p, 1.0f);
    p = fmaf(t, p, 1.0f);
    int e = (((int)n) + 127) << 23;
    return p * __int_as_float(e);
}

// ---------------- merged fp32 -> fp16 conversion (x, W1, W2 in one launch) ----------------
#define N4_X  (NN * KIN / 4)
#define N4_W1 (KIN * HC / 4)
#define N4_W2 (HC * C2 / 4)
__global__ void f2h_all_k(const float* __restrict__ x, const float* __restrict__ W1,
                          const float* __restrict__ W2) {
    int i = blockIdx.x * blockDim.x + threadIdx.x;
    const float* src; __half* dst; int idx;
    if (i < N4_X)                 { src = x;  dst = g_xh;  idx = i; }
    else if (i < N4_X + N4_W1)    { src = W1; dst = g_w1h; idx = i - N4_X; }
    else if (i < N4_X + N4_W1 + N4_W2) { src = W2; dst = g_w2h; idx = i - N4_X - N4_W1; }
    else return;
    float4 v = ((const float4*)src)[idx];
    __half2* d = (__half2*)dst + idx * 2;
    d[0] = __floats2half2_rn(v.x, v.y);
    d[1] = __floats2half2_rn(v.z, v.w);
}

// ---------------- dtype probe + zero counts (fused) ----------------
__global__ void detect_zero_k(const long long* __restrict__ ei64) {
    int t = blockIdx.x * blockDim.x + threadIdx.x;
    if (t < NN) g_cnt[t] = 0;
    if (blockIdx.x == 0) {
        __shared__ int bad;
        if (threadIdx.x == 0) bad = 0;
        __syncthreads();
        for (int i = threadIdx.x; i < 2048; i += blockDim.x) {
            long long v = ei64[i];
            if (v < 0 || v >= NN) bad = 1;
        }
        __syncthreads();
        if (threadIdx.x == 0) g_is64 = bad ? 0 : 1;
    }
}

__device__ __forceinline__ void load_edge(const void* __restrict__ ei, int e, int& s, int& d) {
    if (e >= EE) { s = d = e - EE; return; }
    if (g_is64) {
        const long long* p = (const long long*)ei;
        s = (int)p[e]; d = (int)p[EE + e];
    } else {
        const int* p = (const int*)ei;
        s = p[e]; d = p[EE + e];
    }
}

// ---------------- one-pass bucketing (replaces count+scan+scatter) ----------------
__global__ void bucket_k(const void* __restrict__ ei) {
    int e = blockIdx.x * blockDim.x + threadIdx.x;
    if (e >= ET) return;
    int s, d; load_edge(ei, e, s, d);
    if ((unsigned)d < NN && (unsigned)s < NN) {
        int pos = atomicAdd(&g_cnt[d], 1);
        if (pos < MAXD) g_buck[d * MAXD + pos] = s;
    }
}

// ---------------- fp16 WMMA GEMM 64x64 (BK=32) + fused logits epilogue ----------------
#define BK32 32
__global__ __launch_bounds__(256) void hgemm_fused_k(const __half* __restrict__ A,
                                                     const __half* __restrict__ B,
                                                     __half* __restrict__ Ch,
                                                     const float* __restrict__ attS,
                                                     const float* __restrict__ attD,
                                                     float* __restrict__ asOut,
                                                     float* __restrict__ adOut,
                                                     int HS,
                                                     int M, int N, int K) {
    __shared__ __half Ah[64][48];
    __shared__ __half Bh[32][80];
    __shared__ float  Cs[64][68];
    const int bn = blockIdx.x * 64;
    const int bm = blockIdx.y * 64;
    const int tid = threadIdx.x;
    const int w = tid >> 5;
    const int wm = (w >> 1) * 16;
    const int wn = (w & 1) * 32;

    wmma::fragment<wmma::accumulator, 16, 16, 16, float> c0, c1;
    wmma::fill_fragment(c0, 0.f);
    wmma::fill_fragment(c1, 0.f);

    for (int k0 = 0; k0 < K; k0 += BK32) {
        {
            int row = tid >> 2, col8 = (tid & 3) * 8;
            int gm = bm + row;
            float4 v = make_float4(0.f, 0.f, 0.f, 0.f);
            if (gm < M) v = *(const float4*)&A[(size_t)gm * K + k0 + col8];
            *(float4*)&Ah[row][col8] = v;
        }
        {
            int row = tid >> 3, col8 = (tid & 7) * 8;
            *(float4*)&Bh[row][col8] = *(const float4*)&B[(size_t)(k0 + row) * N + bn + col8];
        }
        __syncthreads();
        wmma::fragment<wmma::matrix_a, 16, 16, 16, __half, wmma::row_major> af;
        wmma::fragment<wmma::matrix_b, 16, 16, 16, __half, wmma::row_major> b0, b1;
#pragma unroll
        for (int kk = 0; kk < BK32; kk += 16) {
            wmma::load_matrix_sync(af, &Ah[wm][kk], 48);
            wmma::load_matrix_sync(b0, &Bh[kk][wn], 80);
            wmma::load_matrix_sync(b1, &Bh[kk][wn + 16], 80);
            wmma::mma_sync(c0, af, b0, c0);
            wmma::mma_sync(c1, af, b1, c1);
        }
        __syncthreads();
    }

    wmma::store_matrix_sync(&Cs[wm][wn],      c0, 68, wmma::mem_row_major);
    wmma::store_matrix_sync(&Cs[wm][wn + 16], c1, 68, wmma::mem_row_major);
    __syncthreads();

    const int tx = tid & 15, ty = tid >> 4;
    float asv[4], adv[4];
#pragma unroll
    for (int j = 0; j < 4; j++) {
        asv[j] = attS[bn + tx * 4 + j];
        adv[j] = attD[bn + tx * 4 + j];
    }
    const int h = blockIdx.x;
#pragma unroll
    for (int i = 0; i < 4; i++) {
        int gm = bm + ty * 4 + i;
        float a0 = Cs[ty * 4 + i][tx * 4 + 0];
        float a1 = Cs[ty * 4 + i][tx * 4 + 1];
        float a2 = Cs[ty * 4 + i][tx * 4 + 2];
        float a3 = Cs[ty * 4 + i][tx * 4 + 3];
        float s = a0 * asv[0] + a1 * asv[1] + a2 * asv[2] + a3 * asv[3];
        float d = a0 * adv[0] + a1 * adv[1] + a2 * adv[2] + a3 * adv[3];
#pragma unroll
        for (int o = 8; o; o >>= 1) {
            s += __shfl_down_sync(0xffffffffu, s, o, 16);
            d += __shfl_down_sync(0xffffffffu, d, o, 16);
        }
        if (gm < M) {
            if (tx == 0) {
                asOut[(size_t)gm * HS + h] = s;
                adOut[(size_t)gm * HS + h] = d;
            }
            __half2* hp = (__half2*)&Ch[(size_t)gm * N + bn + tx * 4];
            hp[0] = __floats2half2_rn(a0, a1);
            hp[1] = __floats2half2_rn(a2, a3);
        }
    }
}

// ---------------- gat1: edge softmax + 2-wide fp16 gather (R15 structure) ----------------
__global__ __launch_bounds__(256) void gat1_k(const float* __restrict__ bias1) {
    const int d = blockIdx.x;
    const int tid = threadIdx.x;
    const int cnt = min(g_cnt[d], MAXD);
    const int base = d * MAXD;

    float loc[H1] = {0.f, 0.f, 0.f, 0.f};
    const int items = cnt * H1;
    for (int i = tid; i < items; i += 256) {
        int j = i >> 2;
        int h = i & 3;
        int s = g_buck[base + j];
        float x = g_as1[s * H1 + h] + g_ad1[d * H1 + h];
        x = (x > 0.f) ? x : 0.2f * x;
        x = fmaxf(x, -60.f);
        float w = fexp(x);
        g_w1c[(base + j) * H1 + h] = w;
        loc[h] += w;
    }
#pragma unroll
    for (int h = 0; h < H1; h++)
#pragma unroll
        for (int o = 16; o; o >>= 1) loc[h] += __shfl_down_sync(0xffffffffu, loc[h], o);
    __shared__ float sw[8][H1];
    if ((tid & 31) == 0)
#pragma unroll
        for (int h = 0; h < H1; h++) sw[tid >> 5][h] = loc[h];
    __syncthreads();
    __shared__ float sinv[H1];
    if (tid < H1) {
        float s = 0.f;
#pragma unroll
        for (int w = 0; w < 8; w++) s += sw[w][tid];
        sinv[tid] = 1.0f / (s + 1e-16f);
    }
    __syncthreads();

    const int eo = tid >> 7;
    const int fi = tid & 127;
    const int f  = fi * 2;
    const int h  = f >> 6;
    const float inv = sinv[h];
    float2 acc = make_float2(0.f, 0.f);
    const __half2* h1h = (const __half2*)g_h1h;
#pragma unroll 4
    for (int j = eo; j < cnt; j += 2) {
        int s = g_buck[base + j];
        float w = g_w1c[(base + j) * H1 + h];
        float2 v = __half22float2(h1h[(size_t)s * (HC / 2) + fi]);
        acc.x += w * v.x;
        acc.y += w * v.y;
    }
    __shared__ float2 part[128];
    if (eo == 1) part[fi] = acc;
    __syncthreads();
    if (eo == 0) {
        acc.x += part[fi].x;
        acc.y += part[fi].y;
        float v0 = acc.x * inv + bias1[f];
        float v1 = acc.y * inv + bias1[f + 1];
        v0 = (v0 > 0.f) ? v0 : expm1f(v0);
        v1 = (v1 > 0.f) ? v1 : expm1f(v1);
        ((__half2*)g_x1h)[(size_t)d * (HC / 2) + fi] = __floats2half2_rn(v0, v1);
    }
}

// ---------------- gat2: edge softmax + 2-wide fp16 gather (R15 structure) ----------------
__global__ __launch_bounds__(64) void gat2_k(const float* __restrict__ bias2,
                                             float* __restrict__ out) {
    const int d = blockIdx.x;
    const int tid = threadIdx.x;
    const int cnt = min(g_cnt[d], MAXD);
    const int base = d * MAXD;

    float loc = 0.f;
    const float ad = g_ad2[d];
    for (int i = tid; i < cnt; i += 64) {
        int s = g_buck[base + i];
        float x = g_as2[s] + ad;
        x = (x > 0.f) ? x : 0.2f * x;
        x = fmaxf(x, -60.f);
        float w = fexp(x);
        g_w2c[base + i] = w;
        loc += w;
    }
#pragma unroll
    for (int o = 16; o; o >>= 1) loc += __shfl_down_sync(0xffffffffu, loc, o);
    __shared__ float sw2[2];
    if ((tid & 31) == 0) sw2[tid >> 5] = loc;
    __syncthreads();
    __shared__ float sinv2;
    if (tid == 0) sinv2 = 1.0f / (sw2[0] + sw2[1] + 1e-16f);
    __syncthreads();

    const int eo = tid >> 5;
    const int fi = tid & 31;
    const int f  = fi * 2;
    const float inv = sinv2;
    float2 acc = make_float2(0.f, 0.f);
    const __half2* h2h = (const __half2*)g_h2h;
#pragma unroll 4
    for (int j = eo; j < cnt; j += 2) {
        int s = g_buck[base + j];
        float w = g_w2c[base + j];
        float2 v = __half22float2(h2h[(size_t)s * (C2 / 2) + fi]);
        acc.x += w * v.x;
        acc.y += w * v.y;
    }
    __shared__ float2 part2[32];
    if (eo == 1) part2[fi] = acc;
    __syncthreads();
    if (eo == 0) {
        acc.x += part2[fi].x;
        acc.y += part2[fi].y;
        out[(size_t)d * C2 + f]     = acc.x * inv + bias2[f];
        out[(size_t)d * C2 + f + 1] = acc.y * inv + bias2[f + 1];
    }
}

// ---------------- launch ----------------
extern "C" void kernel_launch(void* const* d_in, const int* in_sizes, int n_in,
                              void* d_out, int out_size) {
    const float* x   = (const float*)d_in[0];
    const void*  ei  = d_in[1];
    const float* W1  = (const float*)d_in[2];
    const float* as1 = (const float*)d_in[3];
    const float* ad1 = (const float*)d_in[4];
    const float* b1  = (const float*)d_in[5];
    const float* W2  = (const float*)d_in[6];
    const float* as2 = (const float*)d_in[7];
    const float* ad2 = (const float*)d_in[8];
    const float* b2  = (const float*)d_in[9];
    float* out = (float*)d_out;

    // R7 root cause: resolve true device addresses of __device__ symbols
    // used as kernel args (host-shadow writes are silently absorbed via ATS).
    __half *xhp, *w1hp, *w2hp, *h1hp, *x1hp, *h2hp;
    float  *as1p, *ad1p, *as2p, *ad2p;
    cudaGetSymbolAddress((void**)&xhp,  g_xh);
    cudaGetSymbolAddress((void**)&w1hp, g_w1h);
    cudaGetSymbolAddress((void**)&w2hp, g_w2h);
    cudaGetSymbolAddress((void**)&h1hp, g_h1h);
    cudaGetSymbolAddress((void**)&x1hp, g_x1h);
    cudaGetSymbolAddress((void**)&h2hp, g_h2h);
    cudaGetSymbolAddress((void**)&as1p, g_as1);
    cudaGetSymbolAddress((void**)&ad1p, g_ad1);
    cudaGetSymbolAddress((void**)&as2p, g_as2);
    cudaGetSymbolAddress((void**)&ad2p, g_ad2);

    detect_zero_k<<<(NN + 255) / 256, 256>>>((const long long*)ei);
    bucket_k<<<(ET + 255) / 256, 256>>>(ei);

    f2h_all_k<<<(N4_X + N4_W1 + N4_W2 + 255) / 256, 256>>>(x, W1, W2);

    // layer 1
    { dim3 g(HC / 64, (NN + 63) / 64);
      hgemm_fused_k<<<g, 256>>>(xhp, w1hp, h1hp, as1, ad1, as1p, ad1p, H1, NN, HC, KIN); }
    gat1_k<<<NN, 256>>>(b1);

    // layer 2
    { dim3 g(C2 / 64, (NN + 63) / 64);
      hgemm_fused_k<<<g, 256>>>(x1hp, w2hp, h2hp, as2, ad2, as2p, ad2p, 1, NN, C2, HC); }
    gat2_k<<<NN, 64>>>(b2, out);
}